// round 12
// baseline (speedup 1.0000x reference)
#include <cuda_runtime.h>
#include <cuda_fp16.h>
#include <cstdint>

namespace {

constexpr int BB = 256, TT = 512, DD = 64, HH = 128, KC = 256;
constexpr int NROW = BB * TT;            // 131072 (b,t) rows

// g_pre[row][q][j]: q = 0 zpre(+bz), 1 rpre(+br), 2 xmpre(+bh), 3 dh
__device__ float  g_pre[(size_t)NROW * 4 * HH];            // 256 MB
__device__ __half g_act[(size_t)NROW * 192];               // [row][xt|m|d]
// B fragments in mma.m16n8k16 lane order: 448 frags x 32 lanes x uint2
__device__ uint2  g_wfrag[448 * 32];

__device__ __forceinline__ float2 mk2(float x, float y) { return make_float2(x, y); }

__device__ __forceinline__ unsigned pack_h2(float x, float y) {
    __half2 h = __floats2half2_rn(x, y);
    return *reinterpret_cast<unsigned*>(&h);
}

#define MMA16816(d0, d1, d2, d3, a0, a1, a2, a3, b0, b1)                     \
    asm volatile(                                                            \
        "mma.sync.aligned.m16n8k16.row.col.f32.f16.f16.f32 "                 \
        "{%0,%1,%2,%3}, {%4,%5,%6,%7}, {%8,%9}, {%0,%1,%2,%3};"              \
        : "+f"(d0), "+f"(d1), "+f"(d2), "+f"(d3)                             \
        : "r"(a0), "r"(a1), "r"(a2), "r"(a3), "r"(b0), "r"(b1))

// ===========================================================================
// P1: elementwise -> fp16 act matrix [row][ xt(64) | m(64) | d(64) ].
// ===========================================================================
__global__ void __launch_bounds__(256, 1) act_kernel(
    const float* __restrict__ inp,
    const float* __restrict__ Wgx, const float* __restrict__ bgx)
{
    const int row = blockIdx.x * 8 + (threadIdx.x >> 5);
    const int l   = threadIdx.x & 31;
    const int b = row >> 9, t = row & 511;
    const float* ib = inp + ((long)(b * 4) * TT + t) * DD;
    const long CH = (long)TT * DD;
    float2 x  = *(const float2*)(ib + 2 * l);
    float2 xl = *(const float2*)(ib + CH + 2 * l);
    float2 m  = *(const float2*)(ib + 2 * CH + 2 * l);
    float2 d  = *(const float2*)(ib + 3 * CH + 2 * l);
    float  g0 = __ldg(&Wgx[(2 * l) * DD + 2 * l]);
    float  g1 = __ldg(&Wgx[(2 * l + 1) * DD + 2 * l + 1]);
    float2 bx = *(const float2*)(bgx + 2 * l);
    float dx0 = __expf(-fmaxf(fmaf(d.x, g0, bx.x), 0.f));
    float dx1 = __expf(-fmaxf(fmaf(d.y, g1, bx.y), 0.f));
    float xt0 = m.x * x.x + (1.f - m.x) * (dx0 * xl.x);
    float xt1 = m.y * x.y + (1.f - m.y) * (dx1 * xl.y);
    __half2* ga = (__half2*)(g_act + (size_t)row * 192);
    ga[l]      = __floats2half2_rn(xt0, xt1);
    ga[32 + l] = __floats2half2_rn(m.x, m.y);
    ga[64 + l] = __floats2half2_rn(d.x, d.y);
}

// ===========================================================================
// P0: pack weights into mma B-fragment lane order (verified R11).
// ===========================================================================
__global__ void packw_kernel(const float* __restrict__ Wz,
                             const float* __restrict__ Wr,
                             const float* __restrict__ Wh,
                             const float* __restrict__ Wgh) {
    int idx = blockIdx.x * 256 + threadIdx.x;
    int fragIdx = idx >> 5, lane = idx & 31;
    if (fragIdx >= 448) return;
    int g = lane >> 2, t = lane & 3;
    uint2 v;
    if (fragIdx < 384) {
        int q   = fragIdx >> 7;
        int rem = fragIdx & 127;
        int jt = rem >> 3, kt = rem & 7;
        const float* W = (q == 0) ? Wz : (q == 1) ? Wr : Wh;
        int j = jt * 8 + g, k0 = kt * 16;
        auto src = [&](int k) {
            int col = (k < 64) ? k : k + 128;
            return W[j * KC + col];
        };
        v.x = pack_h2(src(k0 + 2 * t),     src(k0 + 2 * t + 1));
        v.y = pack_h2(src(k0 + 2 * t + 8), src(k0 + 2 * t + 9));
    } else {
        int rem = fragIdx - 384;
        int jt = rem >> 2, kt = rem & 3;
        int j = jt * 8 + g, k0 = kt * 16;
        v.x = pack_h2(Wgh[j * DD + k0 + 2 * t],     Wgh[j * DD + k0 + 2 * t + 1]);
        v.y = pack_h2(Wgh[j * DD + k0 + 2 * t + 8], Wgh[j * DD + k0 + 2 * t + 9]);
    }
    g_wfrag[fragIdx * 32 + lane] = v;
}

// ===========================================================================
// P2: HMMA GEMM (verified R11, ~90 us).
// ===========================================================================
constexpr int GS_ACT  = 0;
constexpr int GS_WF   = 51200;
constexpr int GS_BIAS = GS_WF + 114688;
constexpr int GEMM_SMEM = GS_BIAS + 512 * 4;

__global__ void __launch_bounds__(256, 1) gemm_kernel(
    const float* __restrict__ bz, const float* __restrict__ br,
    const float* __restrict__ bh, const float* __restrict__ bgh)
{
    extern __shared__ char sm[];
    __half* sact = (__half*)(sm + GS_ACT);
    uint2*  swf  = (uint2*)(sm + GS_WF);
    float*  sbias = (float*)(sm + GS_BIAS);

    const int tid = threadIdx.x;
    const int row0 = blockIdx.x * 128;

    for (int i = tid; i < 128 * 48; i += 256) {
        int r = i / 48, c = i - r * 48;
        uint2 v = *(const uint2*)(g_act + (size_t)(row0 + r) * 192 + c * 4);
        *(uint2*)(sact + r * 200 + c * 4) = v;
    }
    for (int i = tid; i < 448 * 32 / 2; i += 256)
        ((uint4*)swf)[i] = ((const uint4*)g_wfrag)[i];
    if (tid < 128) {
        sbias[tid] = bz[tid];       sbias[128 + tid] = br[tid];
        sbias[256 + tid] = bh[tid]; sbias[384 + tid] = bgh[tid];
    }
    __syncthreads();

    const int w = tid >> 5, lane = tid & 31;
    const int g = lane >> 2, t = lane & 3;
    const int arow = w * 16 + g;

    uint32_t A[12][4];
    #pragma unroll
    for (int kt = 0; kt < 12; ++kt) {
        int k0 = (kt < 8) ? kt * 16 : 128 + (kt - 8) * 16;
        const __half* p = sact + arow * 200 + k0 + 2 * t;
        A[kt][0] = *(const uint32_t*)(p);
        A[kt][1] = *(const uint32_t*)(p + 8 * 200);
        A[kt][2] = *(const uint32_t*)(p + 8);
        A[kt][3] = *(const uint32_t*)(p + 8 * 200 + 8);
    }

    for (int q = 0; q < 3; ++q) {
        #pragma unroll 4
        for (int jt = 0; jt < 16; ++jt) {
            float d0 = 0.f, d1 = 0.f, d2 = 0.f, d3 = 0.f;
            const uint2* wp = swf + (q * 128 + jt * 8) * 32 + lane;
            #pragma unroll
            for (int kt = 0; kt < 8; ++kt) {
                uint2 b = wp[kt * 32];
                MMA16816(d0, d1, d2, d3,
                         A[kt][0], A[kt][1], A[kt][2], A[kt][3], b.x, b.y);
            }
            int j0 = jt * 8 + 2 * t;
            float2 bb = *(const float2*)&sbias[q * 128 + j0];
            size_t base = (size_t)(row0 + arow) * 512 + q * 128 + j0;
            *(float2*)&g_pre[base]            = mk2(d0 + bb.x, d1 + bb.y);
            *(float2*)&g_pre[base + 8 * 512]  = mk2(d2 + bb.x, d3 + bb.y);
        }
    }
    #pragma unroll 4
    for (int jt = 0; jt < 16; ++jt) {
        float d0 = 0.f, d1 = 0.f, d2 = 0.f, d3 = 0.f;
        const uint2* wp = swf + (384 + jt * 4) * 32 + lane;
        #pragma unroll
        for (int kt = 0; kt < 4; ++kt) {
            uint2 b = wp[kt * 32];
            MMA16816(d0, d1, d2, d3,
                     A[8 + kt][0], A[8 + kt][1], A[8 + kt][2], A[8 + kt][3],
                     b.x, b.y);
        }
        int j0 = jt * 8 + 2 * t;
        float2 bb = *(const float2*)&sbias[384 + j0];
        size_t base = (size_t)(row0 + arow) * 512 + 384 + j0;
        *(float2*)&g_pre[base] =
            mk2(__expf(-fmaxf(d0 + bb.x, 0.f)), __expf(-fmaxf(d1 + bb.y, 0.f)));
        *(float2*)&g_pre[base + 8 * 512] =
            mk2(__expf(-fmaxf(d2 + bb.x, 0.f)), __expf(-fmaxf(d3 + bb.y, 0.f)));
    }
}

// ===========================================================================
// Scan v3: HMMA per step.  NT=256 (8 warps); warp w owns j-tile [16w,16w+16).
// Weights = persistent register A-fragments (no per-step cvts).
// Activations hpre / r*hpre mirrored to fp16 smem; B-fragments via LDS.32,
// row stride 136 halves (272 B) -> conflict-free (g*272+4t distinct mod 128).
// D-frag lands (j,b) on t4==0 lanes; those lanes own the entire epilogue:
// z in regs across stages, h_pre fp32 in regs across steps.
// ===========================================================================
__global__ void __launch_bounds__(256, 1) scan_kernel(
    const float* __restrict__ Wz, const float* __restrict__ Wr,
    const float* __restrict__ Wh,
    float* __restrict__ out)         // [B,T,H]
{
    __shared__ __half hpre_h[8][136];   // rows 0,1 = batches; 2..7 stay zero
    __shared__ __half crh_h [8][136];

    const int tid  = threadIdx.x;
    const int w    = tid >> 5;
    const int lane = tid & 31;
    const int g    = lane >> 2;
    const int t4   = lane & 3;
    const int b0   = blockIdx.x * 2;
    const int j0   = w * 16 + g;
    const int j1   = j0 + 8;
    const bool epi = (t4 == 0);

    // ---- persistent A-fragments over W h-region (cols 64..191) ----
    uint32_t Az[8][4], Ar[8][4], Ah[8][4];
    #pragma unroll
    for (int kt = 0; kt < 8; ++kt) {
        int k = 64 + kt * 16 + 2 * t4;
        float2 a, b;
        a = *(const float2*)&Wz[j0 * KC + k];
        b = *(const float2*)&Wz[j1 * KC + k];
        Az[kt][0] = pack_h2(a.x, a.y); Az[kt][1] = pack_h2(b.x, b.y);
        a = *(const float2*)&Wz[j0 * KC + k + 8];
        b = *(const float2*)&Wz[j1 * KC + k + 8];
        Az[kt][2] = pack_h2(a.x, a.y); Az[kt][3] = pack_h2(b.x, b.y);
        a = *(const float2*)&Wr[j0 * KC + k];
        b = *(const float2*)&Wr[j1 * KC + k];
        Ar[kt][0] = pack_h2(a.x, a.y); Ar[kt][1] = pack_h2(b.x, b.y);
        a = *(const float2*)&Wr[j0 * KC + k + 8];
        b = *(const float2*)&Wr[j1 * KC + k + 8];
        Ar[kt][2] = pack_h2(a.x, a.y); Ar[kt][3] = pack_h2(b.x, b.y);
        a = *(const float2*)&Wh[j0 * KC + k];
        b = *(const float2*)&Wh[j1 * KC + k];
        Ah[kt][0] = pack_h2(a.x, a.y); Ah[kt][1] = pack_h2(b.x, b.y);
        a = *(const float2*)&Wh[j0 * KC + k + 8];
        b = *(const float2*)&Wh[j1 * KC + k + 8];
        Ah[kt][2] = pack_h2(a.x, a.y); Ah[kt][3] = pack_h2(b.x, b.y);
    }

    // zero smem (rows 2..7 remain zero forever -> B cols 2..7 = 0)
    for (int i = tid; i < 8 * 136; i += 256) {
        ((__half*)hpre_h)[i] = __float2half(0.f);
        ((__half*)crh_h)[i]  = __float2half(0.f);
    }

    // ---- per-epi-lane scratch streams: combos c = b + 2*jsel ----
    // tuple(t) = { zpre(t), rpre(t), xmpre(t), dh(t+1) }
    size_t tb[4];
    #pragma unroll
    for (int c = 0; c < 4; ++c)
        tb[c] = ((size_t)(b0 + (c & 1)) * TT) * 512 + ((c >> 1) ? j1 : j0);

    float4 pf_c[1], pf_n[1];   // dummy arrays avoided; use plain float4 x4
    float pz[4], pr[4], px[4], pd[4];      // current tuple
    float nz[4], nr[4], nx[4], nd[4];      // next tuple
    float hown[4];
    if (epi) {
        #pragma unroll
        for (int c = 0; c < 4; ++c) {
            pz[c] = g_pre[tb[c]];
            pr[c] = g_pre[tb[c] + 128];
            px[c] = g_pre[tb[c] + 256];
            pd[c] = g_pre[tb[c] + 512 + 384];          // dh(1)
            nz[c] = g_pre[tb[c] + 512];
            nr[c] = g_pre[tb[c] + 512 + 128];
            nx[c] = g_pre[tb[c] + 512 + 256];
            nd[c] = g_pre[tb[c] + 1024 + 384];         // dh(2)
            hown[c] = 0.f;
        }
    }
    (void)pf_c; (void)pf_n;
    __syncthreads();

    float zg[4];

    for (int t = 0; t < TT; ++t) {
        // ---- stage A: z and r, interleaved chains ----
        {
            float z0 = 0.f, z1 = 0.f, z2 = 0.f, z3 = 0.f;
            float r0 = 0.f, r1 = 0.f, r2 = 0.f, r3 = 0.f;
            #pragma unroll
            for (int kt = 0; kt < 8; ++kt) {
                uint32_t bf0 = *(const uint32_t*)&hpre_h[g][kt * 16 + 2 * t4];
                uint32_t bf1 = *(const uint32_t*)&hpre_h[g][kt * 16 + 2 * t4 + 8];
                MMA16816(z0, z1, z2, z3,
                         Az[kt][0], Az[kt][1], Az[kt][2], Az[kt][3], bf0, bf1);
                MMA16816(r0, r1, r2, r3,
                         Ar[kt][0], Ar[kt][1], Ar[kt][2], Ar[kt][3], bf0, bf1);
            }
            if (epi) {
                // d0=(j0,b0) d1=(j0,b1) d2=(j1,b0) d3=(j1,b1) == combos 0..3
                float zd[4] = {z0, z1, z2, z3};
                float rd[4] = {r0, r1, r2, r3};
                #pragma unroll
                for (int c = 0; c < 4; ++c) {
                    zg[c]   = __fdividef(1.f, 1.f + __expf(-(zd[c] + pz[c])));
                    float r = __fdividef(1.f, 1.f + __expf(-(rd[c] + pr[c])));
                    crh_h[c & 1][(c >> 1) ? j1 : j0] =
                        __float2half(r * hown[c]);
                }
            }
        }
        __syncthreads();                                   // bar 1

        // ---- stage C: Wh_h @ crh (2 accumulator chains) ----
        {
            float c00 = 0.f, c01 = 0.f, c02 = 0.f, c03 = 0.f;
            float c10 = 0.f, c11 = 0.f, c12 = 0.f, c13 = 0.f;
            #pragma unroll
            for (int kt = 0; kt < 8; kt += 2) {
                uint32_t b00 = *(const uint32_t*)&crh_h[g][kt * 16 + 2 * t4];
                uint32_t b01 = *(const uint32_t*)&crh_h[g][kt * 16 + 2 * t4 + 8];
                uint32_t b10 = *(const uint32_t*)&crh_h[g][(kt + 1) * 16 + 2 * t4];
                uint32_t b11 = *(const uint32_t*)&crh_h[g][(kt + 1) * 16 + 2 * t4 + 8];
                MMA16816(c00, c01, c02, c03,
                         Ah[kt][0], Ah[kt][1], Ah[kt][2], Ah[kt][3], b00, b01);
                MMA16816(c10, c11, c12, c13,
                         Ah[kt+1][0], Ah[kt+1][1], Ah[kt+1][2], Ah[kt+1][3],
                         b10, b11);
            }
            if (epi) {
                float cd[4] = {c00 + c10, c01 + c11, c02 + c12, c03 + c13};
                #pragma unroll
                for (int c = 0; c < 4; ++c) {
                    float pre = cd[c] + px[c];
                    float e2  = __expf(2.f * pre);
                    float ht  = 1.f - __fdividef(2.f, e2 + 1.f);   // tanh
                    float hn  = fmaf(zg[c], ht - hown[c], hown[c]);
                    int b = c & 1, j = (c >> 1) ? j1 : j0;
                    out[((size_t)(b0 + b) * TT + t) * HH + j] = hn;
                    float hp = pd[c] * hn;                 // dh(t+1) * h_t
                    hown[c] = hp;
                    hpre_h[b][j] = __float2half(hp);
                    // rotate tuples; issue loads for t+2
                    pz[c] = nz[c]; pr[c] = nr[c]; px[c] = nx[c]; pd[c] = nd[c];
                }
                int t2 = (t + 2 < TT) ? t + 2 : TT - 1;
                int t3 = (t + 3 < TT) ? t + 3 : TT - 1;
                #pragma unroll
                for (int c = 0; c < 4; ++c) {
                    size_t o = tb[c] + (size_t)t2 * 512;
                    nz[c] = g_pre[o];
                    nr[c] = g_pre[o + 128];
                    nx[c] = g_pre[o + 256];
                    nd[c] = g_pre[tb[c] + (size_t)t3 * 512 + 384];
                }
            }
        }
        __syncthreads();                                   // bar 2
    }
}

} // namespace

extern "C" void kernel_launch(void* const* d_in, const int* in_sizes, int n_in,
                              void* d_out, int out_size) {
    const float* inp = (const float*)d_in[0];
    const float* Wgx = (const float*)d_in[1];
    const float* bgx = (const float*)d_in[2];
    const float* Wgh = (const float*)d_in[3];
    const float* bgh = (const float*)d_in[4];
    const float* Wz  = (const float*)d_in[5];
    const float* bz  = (const float*)d_in[6];
    const float* Wr  = (const float*)d_in[7];
    const float* br  = (const float*)d_in[8];
    const float* Wh  = (const float*)d_in[9];
    const float* bh  = (const float*)d_in[10];
    float* out = (float*)d_out;

    act_kernel<<<NROW / 8, 256>>>(inp, Wgx, bgx);
    packw_kernel<<<56, 256>>>(Wz, Wr, Wh, Wgh);
    cudaFuncSetAttribute(gemm_kernel,
                         cudaFuncAttributeMaxDynamicSharedMemorySize, GEMM_SMEM);
    gemm_kernel<<<NROW / 128, 256, GEMM_SMEM>>>(bz, br, bh, bgh);
    scan_kernel<<<BB / 2, 256>>>(Wz, Wr, Wh, out);
}